// round 1
// baseline (speedup 1.0000x reference)
#include <cuda_runtime.h>
#include <math.h>
#include <float.h>

// Problem constants (fixed by the dataset)
constexpr int NMAX = 10000;
constexpr int EMAX = 50000;
constexpr int D    = 32;
constexpr int H    = 4;

// Scratch (no allocations allowed -> __device__ globals)
__device__ float g_max  [NMAX * H];    // per-(node,head) running max of logits
__device__ float g_denom[NMAX * H];    // per-(node,head) softmax denominator
__device__ float g_agg  [NMAX * D];    // per-node unnormalized sum of V*ex
__device__ float g_ex   [EMAX * H];    // per-(edge,head): logit, then exp(logit-max)

__device__ __forceinline__ void atomicMaxF(float* addr, float v) {
    // standard monotone-bit-pattern trick; init value is -FLT_MAX
    if (v >= 0.0f) atomicMax((int*)addr, __float_as_int(v));
    else           atomicMin((unsigned int*)addr, __float_as_uint(v));
}

__device__ __forceinline__ float warpSum32(float x) {
    #pragma unroll
    for (int off = 16; off; off >>= 1)
        x += __shfl_xor_sync(0xffffffffu, x, off);
    return x;
}

// ---------------------------------------------------------------------------
// K0: init scratch
// ---------------------------------------------------------------------------
__global__ void k_init(int N) {
    int i = blockIdx.x * blockDim.x + threadIdx.x;
    if (i < N * D) g_agg[i] = 0.0f;
    if (i < N * H) { g_max[i] = -FLT_MAX; g_denom[i] = 0.0f; }
}

// ---------------------------------------------------------------------------
// K1: per-edge hypernetwork K/V, logits, atomic segment-max.
// One warp per edge; lane = (h*8+d) output element.
// ---------------------------------------------------------------------------
__global__ void __launch_bounds__(256) k_edge(
    const float* __restrict__ in_feat,
    const int*   __restrict__ src,
    const int*   __restrict__ dst,
    const float* __restrict__ skw,
    const float* __restrict__ dkw,
    const float* __restrict__ skb,
    const float* __restrict__ dkb,
    const float* __restrict__ svw,
    const float* __restrict__ dvw,
    const float* __restrict__ svb,
    const float* __restrict__ dvb,
    const float* __restrict__ query,
    float* __restrict__ key_out,
    float* __restrict__ val_out,
    int E)
{
    int gw   = (blockIdx.x * blockDim.x + threadIdx.x) >> 5;
    int lane = threadIdx.x & 31;
    int wl   = threadIdx.x >> 5;
    __shared__ __align__(16) float su[8][D];
    __shared__ __align__(16) float sv[8][D];
    if (gw >= E) return;
    const int e = gw;
    const int s = src[e];
    const int d = dst[e];

    su[wl][lane] = in_feat[(long)s * D + lane];
    sv[wl][lane] = in_feat[(long)d * D + lane];
    __syncwarp();

    const float4* U  = (const float4*)su[wl];
    const float4* Vb = (const float4*)sv[wl];

    const long rb = ((long)e * 32 + lane) * 32;   // this lane's (h,d) row
    const float4* A  = (const float4*)(skw + rb);
    const float4* B  = (const float4*)(dkw + rb);
    const float4* C  = (const float4*)(svw + rb);
    const float4* Dw = (const float4*)(dvw + rb);

    float kacc = 0.0f, vacc = 0.0f;
    #pragma unroll
    for (int k = 0; k < 8; k++) {
        const float4 uu = U[k];
        const float4 vv = Vb[k];
        float4 a = A[k];
        kacc += a.x*uu.x + a.y*uu.y + a.z*uu.z + a.w*uu.w;
        float4 b = B[k];
        kacc += b.x*vv.x + b.y*vv.y + b.z*vv.z + b.w*vv.w;
        float4 c = C[k];
        vacc += c.x*uu.x + c.y*uu.y + c.z*uu.z + c.w*uu.w;
        float4 dd = Dw[k];
        vacc += dd.x*vv.x + dd.y*vv.y + dd.z*vv.z + dd.w*vv.w;
    }
    const long eo = (long)e * 32 + lane;
    kacc += skb[eo] + dkb[eo];
    vacc += svb[eo] + dvb[eo];
    key_out[eo] = kacc;
    val_out[eo] = vacc;

    // logits: per-head dot K[h,:] . query[dst][h,:]  (8-lane groups)
    float p = kacc * query[(long)d * D + lane];
    p += __shfl_xor_sync(0xffffffffu, p, 1);
    p += __shfl_xor_sync(0xffffffffu, p, 2);
    p += __shfl_xor_sync(0xffffffffu, p, 4);
    if ((lane & 7) == 0) {
        int h = lane >> 3;
        g_ex[e * H + h] = p;                 // store raw logit
        atomicMaxF(&g_max[d * H + h], p);
    }
}

// ---------------------------------------------------------------------------
// K2: ex = exp(logit - max); denom += ex; agg += V * ex  (one thread per (e,h))
// ---------------------------------------------------------------------------
__global__ void k_exp_agg(
    const int*   __restrict__ dst,
    const float* __restrict__ val_out,
    int E)
{
    int tid = blockIdx.x * blockDim.x + threadIdx.x;
    if (tid >= E * H) return;
    int e = tid >> 2;
    int h = tid & 3;
    int d = dst[e];
    float ex = expf(g_ex[tid] - g_max[d * H + h]);
    g_ex[tid] = ex;
    atomicAdd(&g_denom[d * H + h], ex);

    const float4* vp = (const float4*)(val_out + (long)e * 32 + h * 8);
    float4 v0 = vp[0], v1 = vp[1];
    float* ag = &g_agg[d * 32 + h * 8];
    atomicAdd(ag + 0, v0.x * ex);
    atomicAdd(ag + 1, v0.y * ex);
    atomicAdd(ag + 2, v0.z * ex);
    atomicAdd(ag + 3, v0.w * ex);
    atomicAdd(ag + 4, v1.x * ex);
    atomicAdd(ag + 5, v1.y * ex);
    atomicAdd(ag + 6, v1.z * ex);
    atomicAdd(ag + 7, v1.w * ex);
}

// ---------------------------------------------------------------------------
// K3: attn = ex / denom[dst]
// ---------------------------------------------------------------------------
__global__ void k_attn(const int* __restrict__ dst, float* __restrict__ attn_out, int E) {
    int tid = blockIdx.x * blockDim.x + threadIdx.x;
    if (tid >= E * H) return;
    int e = tid >> 2;
    int h = tid & 3;
    attn_out[tid] = g_ex[tid] / g_denom[dst[e] * H + h];
}

// ---------------------------------------------------------------------------
// K4: per-node dynamic linear + relu + residual + layernorm. Warp per node.
// ---------------------------------------------------------------------------
__global__ void __launch_bounds__(256) k_node(
    const float* __restrict__ in_feat,
    const float* __restrict__ node_w,
    const float* __restrict__ node_b,
    const float* __restrict__ ln_w,
    const float* __restrict__ ln_b,
    float* __restrict__ out,
    int N)
{
    int gw   = (blockIdx.x * blockDim.x + threadIdx.x) >> 5;
    int lane = threadIdx.x & 31;
    int wl   = threadIdx.x >> 5;
    __shared__ __align__(16) float sa[8][D];
    if (gw >= N) return;
    const int n = gw;

    // normalize aggregation: agg / denom (0 if node has no incoming edges)
    float den = g_denom[n * H + (lane >> 3)];
    float a = (den > 0.0f) ? (g_agg[n * D + lane] / den) : 0.0f;
    sa[wl][lane] = a;
    __syncwarp();

    const float4* Av = (const float4*)sa[wl];
    const float4* W  = (const float4*)(node_w + ((long)n * 32 + lane) * 32);
    float acc = 0.0f;
    #pragma unroll
    for (int k = 0; k < 8; k++) {
        float4 w = W[k];
        float4 x = Av[k];
        acc += w.x*x.x + w.y*x.y + w.z*x.z + w.w*x.w;
    }
    acc += node_b[(long)n * D + lane];
    acc = fmaxf(acc, 0.0f);

    float x = in_feat[(long)n * D + lane] + acc;
    float mu = warpSum32(x) * (1.0f / 32.0f);
    float xm = x - mu;
    float var = warpSum32(xm * xm) * (1.0f / 32.0f);
    float y = xm * rsqrtf(var + 1e-5f) * ln_w[lane] + ln_b[lane];
    out[(long)n * D + lane] = y;
}

// ---------------------------------------------------------------------------
extern "C" void kernel_launch(void* const* d_in, const int* in_sizes, int n_in,
                              void* d_out, int out_size) {
    const float* in_feat = (const float*)d_in[0];
    const int*   src     = (const int*)  d_in[1];
    const int*   dst     = (const int*)  d_in[2];
    const float* skw     = (const float*)d_in[3];
    const float* dkw     = (const float*)d_in[4];
    const float* skb     = (const float*)d_in[5];
    const float* dkb     = (const float*)d_in[6];
    const float* svw     = (const float*)d_in[7];
    const float* dvw     = (const float*)d_in[8];
    const float* svb     = (const float*)d_in[9];
    const float* dvb     = (const float*)d_in[10];
    const float* query   = (const float*)d_in[11];
    const float* node_w  = (const float*)d_in[12];
    const float* node_b  = (const float*)d_in[13];
    const float* ln_w    = (const float*)d_in[14];
    const float* ln_b    = (const float*)d_in[15];

    const int N = in_sizes[0] / D;   // 10000
    const int E = in_sizes[1];       // 50000

    float* out_ptr  = (float*)d_out;                 // (N, 32)
    float* key_ptr  = out_ptr + (long)N * D;         // (E, 32)
    float* val_ptr  = key_ptr + (long)E * D;         // (E, 32)
    float* attn_ptr = val_ptr + (long)E * D;         // (E, 4)

    k_init<<<(N * D + 255) / 256, 256>>>(N);
    k_edge<<<(E + 7) / 8, 256>>>(in_feat, src, dst, skw, dkw, skb, dkb,
                                 svw, dvw, svb, dvb, query,
                                 key_ptr, val_ptr, E);
    k_exp_agg<<<(E * H + 255) / 256, 256>>>(dst, val_ptr, E);
    k_attn<<<(E * H + 255) / 256, 256>>>(dst, attn_ptr, E);
    k_node<<<(N + 7) / 8, 256>>>(in_feat, node_w, node_b, ln_w, ln_b, out_ptr, N);
}

// round 2
// speedup vs baseline: 1.4140x; 1.4140x over previous
#include <cuda_runtime.h>
#include <math.h>
#include <float.h>

constexpr int NMAX = 10000;
constexpr int EMAX = 50000;
constexpr int D    = 32;
constexpr int H    = 4;

// Scratch (no allocations allowed -> __device__ globals)
__device__ float g_max  [NMAX * H];
__device__ float g_denom[NMAX * H];
__device__ float g_agg  [NMAX * D];
__device__ float g_ex   [EMAX * H];

__device__ __forceinline__ void atomicMaxF(float* addr, float v) {
    if (v >= 0.0f) atomicMax((int*)addr, __float_as_int(v));
    else           atomicMin((unsigned int*)addr, __float_as_uint(v));
}

__device__ __forceinline__ float warpSum32(float x) {
    #pragma unroll
    for (int off = 16; off; off >>= 1)
        x += __shfl_xor_sync(0xffffffffu, x, off);
    return x;
}

__device__ __forceinline__ float dot4(float4 a, float4 b) {
    return a.x*b.x + a.y*b.y + a.z*b.z + a.w*b.w;
}

// ---------------------------------------------------------------------------
// K0: init scratch
// ---------------------------------------------------------------------------
__global__ void k_init(int N) {
    int i = blockIdx.x * blockDim.x + threadIdx.x;
    if (i < N * D) g_agg[i] = 0.0f;
    if (i < N * H) { g_max[i] = -FLT_MAX; g_denom[i] = 0.0f; }
}

// ---------------------------------------------------------------------------
// K1: per-edge hypernetwork K/V, logits, atomic segment-max.
// One warp per edge. Fully-coalesced weight loads:
//   instruction i loads float4 at (e*1024 + i*128 + lane*4) floats
//   -> warp covers 512B contiguous = 4 full 128B lines per instruction.
// Lane L holds chunk (row = 4i + L/8, colchunk = L%8). Row-dot reduced over
// the 8-lane group via shfl_xor, placed into per-warp smem transpose buffer.
// ---------------------------------------------------------------------------
__global__ void __launch_bounds__(256) k_edge(
    const float* __restrict__ in_feat,
    const int*   __restrict__ src,
    const int*   __restrict__ dst,
    const float* __restrict__ skw,
    const float* __restrict__ dkw,
    const float* __restrict__ skb,
    const float* __restrict__ dkb,
    const float* __restrict__ svw,
    const float* __restrict__ dvw,
    const float* __restrict__ svb,
    const float* __restrict__ dvb,
    const float* __restrict__ query,
    float* __restrict__ key_out,
    float* __restrict__ val_out,
    int E)
{
    const int gw   = blockIdx.x * 8 + (threadIdx.x >> 5);
    const int lane = threadIdx.x & 31;
    const int wl   = threadIdx.x >> 5;
    __shared__ float kbuf[8][32];
    __shared__ float vbuf[8][32];
    if (gw >= E) return;
    const int e = gw;
    const int s = src[e];
    const int d = dst[e];

    // each lane needs u/v chunk (lane%8): 4 floats
    const float4* inf4 = (const float4*)in_feat;
    const int c = lane & 7;
    const float4 u4 = inf4[(long)s * 8 + c];
    const float4 v4 = inf4[(long)d * 8 + c];

    const float4* A  = (const float4*)skw + (long)e * 256;
    const float4* B  = (const float4*)dkw + (long)e * 256;
    const float4* Cw = (const float4*)svw + (long)e * 256;
    const float4* Dw = (const float4*)dvw + (long)e * 256;

    #pragma unroll
    for (int i = 0; i < 8; i++) {
        const int idx = i * 32 + lane;
        float4 a  = A[idx];
        float4 b  = B[idx];
        float4 cc = Cw[idx];
        float4 dd = Dw[idx];
        float pk = dot4(a, u4) + dot4(b, v4);
        float pv = dot4(cc, u4) + dot4(dd, v4);
        // reduce over the 8-lane group (chunks of one row)
        pk += __shfl_xor_sync(0xffffffffu, pk, 1);
        pv += __shfl_xor_sync(0xffffffffu, pv, 1);
        pk += __shfl_xor_sync(0xffffffffu, pk, 2);
        pv += __shfl_xor_sync(0xffffffffu, pv, 2);
        pk += __shfl_xor_sync(0xffffffffu, pk, 4);
        pv += __shfl_xor_sync(0xffffffffu, pv, 4);
        if (c == 0) {
            const int row = i * 4 + (lane >> 3);
            kbuf[wl][row] = pk;
            vbuf[wl][row] = pv;
        }
    }
    __syncwarp();

    const long eo = (long)e * 32 + lane;
    float kacc = kbuf[wl][lane] + skb[eo] + dkb[eo];
    float vacc = vbuf[wl][lane] + svb[eo] + dvb[eo];
    key_out[eo] = kacc;
    val_out[eo] = vacc;

    // logits: per-head dot K[h,:] . query[dst][h,:] (8-lane groups)
    float p = kacc * query[(long)d * D + lane];
    p += __shfl_xor_sync(0xffffffffu, p, 1);
    p += __shfl_xor_sync(0xffffffffu, p, 2);
    p += __shfl_xor_sync(0xffffffffu, p, 4);
    if ((lane & 7) == 0) {
        int h = lane >> 3;
        g_ex[e * H + h] = p;
        atomicMaxF(&g_max[d * H + h], p);
    }
}

// ---------------------------------------------------------------------------
// K2: ex = exp(logit - max); denom += ex; agg += V * ex  (one thread per (e,h))
// ---------------------------------------------------------------------------
__global__ void k_exp_agg(
    const int*   __restrict__ dst,
    const float* __restrict__ val_out,
    int E)
{
    int tid = blockIdx.x * blockDim.x + threadIdx.x;
    if (tid >= E * H) return;
    int e = tid >> 2;
    int h = tid & 3;
    int d = dst[e];
    float ex = expf(g_ex[tid] - g_max[d * H + h]);
    g_ex[tid] = ex;
    atomicAdd(&g_denom[d * H + h], ex);

    const float4* vp = (const float4*)(val_out + (long)e * 32 + h * 8);
    float4 v0 = vp[0], v1 = vp[1];
    float* ag = &g_agg[d * 32 + h * 8];
    atomicAdd(ag + 0, v0.x * ex);
    atomicAdd(ag + 1, v0.y * ex);
    atomicAdd(ag + 2, v0.z * ex);
    atomicAdd(ag + 3, v0.w * ex);
    atomicAdd(ag + 4, v1.x * ex);
    atomicAdd(ag + 5, v1.y * ex);
    atomicAdd(ag + 6, v1.z * ex);
    atomicAdd(ag + 7, v1.w * ex);
}

// ---------------------------------------------------------------------------
// K3 (fused): attn normalize  AND  per-node linear+relu+residual+layernorm.
// Both depend only on K2's completed denom/agg. Block range selects role.
// ---------------------------------------------------------------------------
__global__ void __launch_bounds__(256) k_tail(
    const int*   __restrict__ dst,
    float* __restrict__ attn_out,
    const float* __restrict__ in_feat,
    const float* __restrict__ node_w,
    const float* __restrict__ node_b,
    const float* __restrict__ ln_w,
    const float* __restrict__ ln_b,
    float* __restrict__ out,
    int N, int E, int attnBlocks)
{
    if ((int)blockIdx.x < attnBlocks) {
        // ---- attn = ex / denom[dst] ----
        int tid = blockIdx.x * blockDim.x + threadIdx.x;
        if (tid >= E * H) return;
        int e = tid >> 2;
        int h = tid & 3;
        attn_out[tid] = g_ex[tid] / g_denom[dst[e] * H + h];
        return;
    }

    // ---- node: warp per node ----
    const int lane = threadIdx.x & 31;
    const int wl   = threadIdx.x >> 5;
    const int n    = ((int)blockIdx.x - attnBlocks) * 8 + wl;
    __shared__ __align__(16) float sa[8][D];
    if (n >= N) return;

    float den = g_denom[n * H + (lane >> 3)];
    float a = (den > 0.0f) ? (g_agg[n * D + lane] / den) : 0.0f;
    sa[wl][lane] = a;
    __syncwarp();

    const float4* Av = (const float4*)sa[wl];
    const float4* W  = (const float4*)(node_w + ((long)n * 32 + lane) * 32);
    float acc = 0.0f;
    #pragma unroll
    for (int k = 0; k < 8; k++) {
        float4 w = W[k];
        float4 x = Av[k];
        acc += w.x*x.x + w.y*x.y + w.z*x.z + w.w*x.w;
    }
    acc += node_b[(long)n * D + lane];
    acc = fmaxf(acc, 0.0f);

    float x = in_feat[(long)n * D + lane] + acc;
    float mu = warpSum32(x) * (1.0f / 32.0f);
    float xm = x - mu;
    float var = warpSum32(xm * xm) * (1.0f / 32.0f);
    float y = xm * rsqrtf(var + 1e-5f) * ln_w[lane] + ln_b[lane];
    out[(long)n * D + lane] = y;
}

// ---------------------------------------------------------------------------
extern "C" void kernel_launch(void* const* d_in, const int* in_sizes, int n_in,
                              void* d_out, int out_size) {
    const float* in_feat = (const float*)d_in[0];
    const int*   src     = (const int*)  d_in[1];
    const int*   dst     = (const int*)  d_in[2];
    const float* skw     = (const float*)d_in[3];
    const float* dkw     = (const float*)d_in[4];
    const float* skb     = (const float*)d_in[5];
    const float* dkb     = (const float*)d_in[6];
    const float* svw     = (const float*)d_in[7];
    const float* dvw     = (const float*)d_in[8];
    const float* svb     = (const float*)d_in[9];
    const float* dvb     = (const float*)d_in[10];
    const float* query   = (const float*)d_in[11];
    const float* node_w  = (const float*)d_in[12];
    const float* node_b  = (const float*)d_in[13];
    const float* ln_w    = (const float*)d_in[14];
    const float* ln_b    = (const float*)d_in[15];

    const int N = in_sizes[0] / D;   // 10000
    const int E = in_sizes[1];       // 50000

    float* out_ptr  = (float*)d_out;
    float* key_ptr  = out_ptr + (long)N * D;
    float* val_ptr  = key_ptr + (long)E * D;
    float* attn_ptr = val_ptr + (long)E * D;

    const int attnBlocks = (E * H + 255) / 256;
    const int nodeBlocks = (N + 7) / 8;

    k_init<<<(N * D + 255) / 256, 256>>>(N);
    k_edge<<<(E + 7) / 8, 256>>>(in_feat, src, dst, skw, dkw, skb, dkb,
                                 svw, dvw, svb, dvb, query,
                                 key_ptr, val_ptr, E);
    k_exp_agg<<<(E * H + 255) / 256, 256>>>(dst, val_ptr, E);
    k_tail<<<attnBlocks + nodeBlocks, 256>>>(dst, attn_ptr, in_feat,
                                             node_w, node_b, ln_w, ln_b,
                                             out_ptr, N, E, attnBlocks);
}

// round 3
// speedup vs baseline: 1.4756x; 1.0436x over previous
#include <cuda_runtime.h>
#include <math.h>
#include <float.h>

constexpr int NMAX = 10000;
constexpr int EMAX = 50000;
constexpr int D    = 32;
constexpr int H    = 4;

// Scratch (no allocations allowed -> __device__ globals)
__device__ float g_max  [NMAX * H];
__device__ float g_denom[NMAX * H];
__device__ float g_agg  [NMAX * D];
__device__ float g_ex   [EMAX * H];

__device__ __forceinline__ void atomicMaxF(float* addr, float v) {
    if (v >= 0.0f) atomicMax((int*)addr, __float_as_int(v));
    else           atomicMin((unsigned int*)addr, __float_as_uint(v));
}

__device__ __forceinline__ float warpSum32(float x) {
    #pragma unroll
    for (int off = 16; off; off >>= 1)
        x += __shfl_xor_sync(0xffffffffu, x, off);
    return x;
}

__device__ __forceinline__ float dot4(float4 a, float4 b) {
    return a.x*b.x + a.y*b.y + a.z*b.z + a.w*b.w;
}

// ---------------------------------------------------------------------------
// K0: init scratch
// ---------------------------------------------------------------------------
__global__ void k_init(int N) {
    int i = blockIdx.x * blockDim.x + threadIdx.x;
    if (i < N * D) g_agg[i] = 0.0f;
    if (i < N * H) { g_max[i] = -FLT_MAX; g_denom[i] = 0.0f; }
}

// ---------------------------------------------------------------------------
// K1: per-edge hypernetwork K/V, logits, atomic segment-max.
// One warp per edge, fully-coalesced weight loads (warp instruction = 512B
// contiguous = 4 full 128B lines). Lane holds (row=4i+lane/8, chunk=lane%8);
// row-dot reduced over the 8-lane group via shfl_xor.
// ---------------------------------------------------------------------------
__global__ void __launch_bounds__(256) k_edge(
    const float* __restrict__ in_feat,
    const int*   __restrict__ src,
    const int*   __restrict__ dst,
    const float* __restrict__ skw,
    const float* __restrict__ dkw,
    const float* __restrict__ skb,
    const float* __restrict__ dkb,
    const float* __restrict__ svw,
    const float* __restrict__ dvw,
    const float* __restrict__ svb,
    const float* __restrict__ dvb,
    const float* __restrict__ query,
    float* __restrict__ key_out,
    float* __restrict__ val_out,
    int E)
{
    const int gw   = blockIdx.x * 8 + (threadIdx.x >> 5);
    const int lane = threadIdx.x & 31;
    const int wl   = threadIdx.x >> 5;
    __shared__ float kbuf[8][32];
    __shared__ float vbuf[8][32];
    if (gw >= E) return;
    const int e = gw;
    const int s = src[e];
    const int d = dst[e];

    const float4* inf4 = (const float4*)in_feat;
    const int c = lane & 7;
    const float4 u4 = inf4[(long)s * 8 + c];
    const float4 v4 = inf4[(long)d * 8 + c];

    const float4* A  = (const float4*)skw + (long)e * 256;
    const float4* B  = (const float4*)dkw + (long)e * 256;
    const float4* Cw = (const float4*)svw + (long)e * 256;
    const float4* Dw = (const float4*)dvw + (long)e * 256;

    #pragma unroll
    for (int i = 0; i < 8; i++) {
        const int idx = i * 32 + lane;
        float4 a  = A[idx];
        float4 b  = B[idx];
        float4 cc = Cw[idx];
        float4 dd = Dw[idx];
        float pk = dot4(a, u4) + dot4(b, v4);
        float pv = dot4(cc, u4) + dot4(dd, v4);
        pk += __shfl_xor_sync(0xffffffffu, pk, 1);
        pv += __shfl_xor_sync(0xffffffffu, pv, 1);
        pk += __shfl_xor_sync(0xffffffffu, pk, 2);
        pv += __shfl_xor_sync(0xffffffffu, pv, 2);
        pk += __shfl_xor_sync(0xffffffffu, pk, 4);
        pv += __shfl_xor_sync(0xffffffffu, pv, 4);
        if (c == 0) {
            const int row = i * 4 + (lane >> 3);
            kbuf[wl][row] = pk;
            vbuf[wl][row] = pv;
        }
    }
    __syncwarp();

    const long eo = (long)e * 32 + lane;
    float kacc = kbuf[wl][lane] + skb[eo] + dkb[eo];
    float vacc = vbuf[wl][lane] + svb[eo] + dvb[eo];
    key_out[eo] = kacc;
    val_out[eo] = vacc;

    float p = kacc * query[(long)d * D + lane];
    p += __shfl_xor_sync(0xffffffffu, p, 1);
    p += __shfl_xor_sync(0xffffffffu, p, 2);
    p += __shfl_xor_sync(0xffffffffu, p, 4);
    if ((lane & 7) == 0) {
        int h = lane >> 3;
        g_ex[e * H + h] = p;
        atomicMaxF(&g_max[d * H + h], p);
    }
}

// ---------------------------------------------------------------------------
// K2: ex = exp(logit - max); denom += ex; agg += V * ex  (one thread per (e,h))
// ---------------------------------------------------------------------------
__global__ void k_exp_agg(
    const int*   __restrict__ dst,
    const float* __restrict__ val_out,
    int E)
{
    int tid = blockIdx.x * blockDim.x + threadIdx.x;
    if (tid >= E * H) return;
    int e = tid >> 2;
    int h = tid & 3;
    int d = dst[e];
    float ex = expf(g_ex[tid] - g_max[d * H + h]);
    g_ex[tid] = ex;
    atomicAdd(&g_denom[d * H + h], ex);

    const float4* vp = (const float4*)(val_out + (long)e * 32 + h * 8);
    float4 v0 = vp[0], v1 = vp[1];
    float* ag = &g_agg[d * 32 + h * 8];
    atomicAdd(ag + 0, v0.x * ex);
    atomicAdd(ag + 1, v0.y * ex);
    atomicAdd(ag + 2, v0.z * ex);
    atomicAdd(ag + 3, v0.w * ex);
    atomicAdd(ag + 4, v1.x * ex);
    atomicAdd(ag + 5, v1.y * ex);
    atomicAdd(ag + 6, v1.z * ex);
    atomicAdd(ag + 7, v1.w * ex);
}

// ---------------------------------------------------------------------------
// K3 (fused): attn normalize AND node linear+relu+residual+layernorm.
// Node GEMV now uses the coalesced-load + shfl-reduce scheme (same as k_edge):
// warp instruction i covers node_w[n, 4i..4i+3, :] = 512B contiguous.
// ---------------------------------------------------------------------------
__global__ void __launch_bounds__(256) k_tail(
    const int*   __restrict__ dst,
    float* __restrict__ attn_out,
    const float* __restrict__ in_feat,
    const float* __restrict__ node_w,
    const float* __restrict__ node_b,
    const float* __restrict__ ln_w,
    const float* __restrict__ ln_b,
    float* __restrict__ out,
    int N, int E, int attnBlocks)
{
    if ((int)blockIdx.x < attnBlocks) {
        int tid = blockIdx.x * blockDim.x + threadIdx.x;
        if (tid >= E * H) return;
        int e = tid >> 2;
        int h = tid & 3;
        attn_out[tid] = g_ex[tid] / g_denom[dst[e] * H + h];
        return;
    }

    // ---- node: warp per node ----
    const int lane = threadIdx.x & 31;
    const int wl   = threadIdx.x >> 5;
    const int n    = ((int)blockIdx.x - attnBlocks) * 8 + wl;
    __shared__ __align__(16) float sa[8][D];
    __shared__ float obuf[8][32];
    if (n >= N) return;

    // normalized aggregation into smem
    float den = g_denom[n * H + (lane >> 3)];
    float a = (den > 0.0f) ? (g_agg[n * D + lane] / den) : 0.0f;
    sa[wl][lane] = a;
    __syncwarp();

    // this lane's agg chunk (c = lane%8, 4 floats)
    const int c = lane & 7;
    const float4 x4 = ((const float4*)sa[wl])[c];

    // coalesced GEMV: instruction i loads float4 at n*1024 + i*128 + lane*4
    const float4* W = (const float4*)node_w + (long)n * 256;
    #pragma unroll
    for (int i = 0; i < 8; i++) {
        float4 w = W[i * 32 + lane];
        float p = dot4(w, x4);
        p += __shfl_xor_sync(0xffffffffu, p, 1);
        p += __shfl_xor_sync(0xffffffffu, p, 2);
        p += __shfl_xor_sync(0xffffffffu, p, 4);
        if (c == 0) obuf[wl][i * 4 + (lane >> 3)] = p;
    }
    __syncwarp();

    float acc = obuf[wl][lane] + node_b[(long)n * D + lane];
    acc = fmaxf(acc, 0.0f);

    float x = in_feat[(long)n * D + lane] + acc;
    float mu = warpSum32(x) * (1.0f / 32.0f);
    float xm = x - mu;
    float var = warpSum32(xm * xm) * (1.0f / 32.0f);
    float y = xm * rsqrtf(var + 1e-5f) * ln_w[lane] + ln_b[lane];
    out[(long)n * D + lane] = y;
}

// ---------------------------------------------------------------------------
extern "C" void kernel_launch(void* const* d_in, const int* in_sizes, int n_in,
                              void* d_out, int out_size) {
    const float* in_feat = (const float*)d_in[0];
    const int*   src     = (const int*)  d_in[1];
    const int*   dst     = (const int*)  d_in[2];
    const float* skw     = (const float*)d_in[3];
    const float* dkw     = (const float*)d_in[4];
    const float* skb     = (const float*)d_in[5];
    const float* dkb     = (const float*)d_in[6];
    const float* svw     = (const float*)d_in[7];
    const float* dvw     = (const float*)d_in[8];
    const float* svb     = (const float*)d_in[9];
    const float* dvb     = (const float*)d_in[10];
    const float* query   = (const float*)d_in[11];
    const float* node_w  = (const float*)d_in[12];
    const float* node_b  = (const float*)d_in[13];
    const float* ln_w    = (const float*)d_in[14];
    const float* ln_b    = (const float*)d_in[15];

    const int N = in_sizes[0] / D;   // 10000
    const int E = in_sizes[1];       // 50000

    float* out_ptr  = (float*)d_out;
    float* key_ptr  = out_ptr + (long)N * D;
    float* val_ptr  = key_ptr + (long)E * D;
    float* attn_ptr = val_ptr + (long)E * D;

    const int attnBlocks = (E * H + 255) / 256;
    const int nodeBlocks = (N + 7) / 8;

    k_init<<<(N * D + 255) / 256, 256>>>(N);
    k_edge<<<(E + 7) / 8, 256>>>(in_feat, src, dst, skw, dkw, skb, dkb,
                                 svw, dvw, svb, dvb, query,
                                 key_ptr, val_ptr, E);
    k_exp_agg<<<(E * H + 255) / 256, 256>>>(dst, val_ptr, E);
    k_tail<<<attnBlocks + nodeBlocks, 256>>>(dst, attn_ptr, in_feat,
                                             node_w, node_b, ln_w, ln_b,
                                             out_ptr, N, E, attnBlocks);
}